// round 8
// baseline (speedup 1.0000x reference)
#include <cuda_runtime.h>

// B=8, L=96, H=8, E=64, EH=128. Rows per task = 32 (half of B*H=64).
#define NT 256
#define NTASKS 384

typedef unsigned long long ull;

__device__ int g_counter;

__global__ void zero_counter_kernel() { g_counter = 0; }

__device__ __forceinline__ ull pack2(float lo, float hi) {
    ull r; asm("mov.b64 %0, {%1, %2};" : "=l"(r) : "f"(lo), "f"(hi)); return r;
}
__device__ __forceinline__ void unpack2(ull v, float& lo, float& hi) {
    asm("mov.b64 {%0, %1}, %2;" : "=f"(lo), "=f"(hi) : "l"(v));
}
__device__ __forceinline__ void ffma2(ull& acc, ull a, ull b) {
    asm("fma.rn.f32x2 %0, %1, %2, %0;" : "+l"(acc) : "l"(a), "l"(b));
}
__device__ __forceinline__ float tanh_ap(float x) {
    float y; asm("tanh.approx.f32 %0, %1;" : "=f"(y) : "f"(x)); return y;
}

// GEMM1 + tanh: sH[c*32+r] = tanh(b1[c] + sum_k A[k*32+r] * sW1[k*128+c])
// r<32, c<128, k<64. 256 threads, tile 2 rows x 8 cols.
// A may alias sH[0:2048] (the arg region); ibar=true inserts the barrier
// between the (complete) read phase and the write phase.
__device__ __noinline__ void gemm1(const float* A,
                                   const float* __restrict__ sW1,
                                   float* sH,
                                   const float* __restrict__ gb1,
                                   int t, bool ibar)
{
    const int r0 = (t & 15) * 2;
    const int c0 = (t >> 4) * 8;
    ull acc[2][4];
#pragma unroll
    for (int j = 0; j < 4; j++) {
        ull b = pack2(__ldg(gb1 + c0 + 2 * j), __ldg(gb1 + c0 + 2 * j + 1));
        acc[0][j] = b; acc[1][j] = b;
    }
#pragma unroll 16
    for (int k = 0; k < 64; k++) {
        float2 a = *(const float2*)(A + k * 32 + r0);
        ull ap0 = pack2(a.x, a.x), ap1 = pack2(a.y, a.y);
        ulonglong2 w01 = *(const ulonglong2*)(sW1 + k * 128 + c0);
        ulonglong2 w23 = *(const ulonglong2*)(sW1 + k * 128 + c0 + 4);
        ffma2(acc[0][0], ap0, w01.x); ffma2(acc[0][1], ap0, w01.y);
        ffma2(acc[0][2], ap0, w23.x); ffma2(acc[0][3], ap0, w23.y);
        ffma2(acc[1][0], ap1, w01.x); ffma2(acc[1][1], ap1, w01.y);
        ffma2(acc[1][2], ap1, w23.x); ffma2(acc[1][3], ap1, w23.y);
    }
    if (ibar) __syncthreads();
#pragma unroll
    for (int j = 0; j < 4; j++) {
        float l0, h0, l1, h1;
        unpack2(acc[0][j], l0, h0);
        unpack2(acc[1][j], l1, h1);
        *(float2*)(sH + (c0 + 2 * j) * 32 + r0)     = make_float2(tanh_ap(l0), tanh_ap(l1));
        *(float2*)(sH + (c0 + 2 * j + 1) * 32 + r0) = make_float2(tanh_ap(h0), tanh_ap(h1));
    }
}

// GEMM2 + fused RK4 epilogue. k[e][r] = b2[e] + sum_c sH[c*32+r] * sW2[c*64+e]
// mode 0: sK1=k;             arg(=sH[0:2048]) = y + (dt/3) k
// mode 1: sK2=k;             arg = y + dt*k - (dt/3) k1
// mode 2: sK1 = k1+3(k2+k);  arg = y + dt*(k1 - k2 + k)
// mode 3: sY += (dt/8)*(S + k)    (S = sK1 from mode 2)
// Each thread owns the same (e,r) tiles in every call, so state read-modify-
// writes are same-thread; the internal barrier only protects the arg-region
// writes against other threads' reads of sH in the mainloop.
__device__ __noinline__ void gemm2(int mode, float dt,
                                   float* sH,
                                   const float* __restrict__ sW2,
                                   float* __restrict__ sY,
                                   float* __restrict__ sK1,
                                   float* __restrict__ sK2,
                                   const float* __restrict__ gb2,
                                   int t)
{
    const int r0 = (t & 15) * 2;
    const int e0 = (t >> 4) * 4;
    ull acc[2][2];
    {
        ull b0 = pack2(__ldg(gb2 + e0),     __ldg(gb2 + e0 + 1));
        ull b1 = pack2(__ldg(gb2 + e0 + 2), __ldg(gb2 + e0 + 3));
        acc[0][0] = b0; acc[1][0] = b0; acc[0][1] = b1; acc[1][1] = b1;
    }
#pragma unroll 16
    for (int c = 0; c < 128; c++) {
        float2 a = *(const float2*)(sH + c * 32 + r0);
        ull ap0 = pack2(a.x, a.x), ap1 = pack2(a.y, a.y);
        ulonglong2 w = *(const ulonglong2*)(sW2 + c * 64 + e0);
        ffma2(acc[0][0], ap0, w.x); ffma2(acc[0][1], ap0, w.y);
        ffma2(acc[1][0], ap1, w.x); ffma2(acc[1][1], ap1, w.y);
    }
    if (mode != 3) __syncthreads();
    float kv0[4], kv1[4];
    unpack2(acc[0][0], kv0[0], kv0[1]); unpack2(acc[0][1], kv0[2], kv0[3]);
    unpack2(acc[1][0], kv1[0], kv1[1]); unpack2(acc[1][1], kv1[2], kv1[3]);
    const float dt3 = dt * (1.0f / 3.0f);
    const float dt8 = dt * 0.125f;
#pragma unroll
    for (int j = 0; j < 4; j++) {
        const int ix = (e0 + j) * 32 + r0;
        float kx = kv0[j], ky = kv1[j];
        if (mode == 0) {
            float2 y = *(const float2*)(sY + ix);
            *(float2*)(sK1 + ix) = make_float2(kx, ky);
            *(float2*)(sH + ix) = make_float2(y.x + dt3 * kx, y.y + dt3 * ky);
        } else if (mode == 1) {
            float2 y  = *(const float2*)(sY + ix);
            float2 k1 = *(const float2*)(sK1 + ix);
            *(float2*)(sK2 + ix) = make_float2(kx, ky);
            *(float2*)(sH + ix) = make_float2(y.x + dt * kx - dt3 * k1.x,
                                              y.y + dt * ky - dt3 * k1.y);
        } else if (mode == 2) {
            float2 y  = *(const float2*)(sY + ix);
            float2 k1 = *(const float2*)(sK1 + ix);
            float2 k2 = *(const float2*)(sK2 + ix);
            *(float2*)(sK1 + ix) = make_float2(k1.x + 3.0f * (k2.x + kx),
                                               k1.y + 3.0f * (k2.y + ky));
            *(float2*)(sH + ix) = make_float2(y.x + dt * (k1.x - k2.x + kx),
                                              y.y + dt * (k1.y - k2.y + ky));
        } else {
            float2 y = *(const float2*)(sY + ix);
            float2 S = *(const float2*)(sK1 + ix);
            *(float2*)(sY + ix) = make_float2(y.x + dt8 * (S.x + kx),
                                              y.y + dt8 * (S.y + ky));
        }
    }
}

__global__ void __launch_bounds__(NT, 2) ode_kernel(
    const float* __restrict__ gx, const float* __restrict__ gts,
    const float* __restrict__ gW1, const float* __restrict__ gb1,
    const float* __restrict__ gW2, const float* __restrict__ gb2,
    float2* __restrict__ out)
{
    extern __shared__ float sm[];
    float* sW1 = sm;             // 8192  [k*128+c]
    float* sW2 = sW1 + 8192;     // 8192  [c*64+e]
    float* sH  = sW2 + 8192;     // 4096  [c*32+r]; first 2048 double as arg [e*32+r]
    float* sY  = sH + 4096;      // 2048  [e*32+r]
    float* sK1 = sY + 2048;      // 2048
    float* sK2 = sK1 + 2048;     // 2048
    __shared__ int sTask;

    const int t = threadIdx.x;
    for (int q = t; q < 8192; q += NT) { sW1[q] = gW1[q]; sW2[q] = gW2[q]; }

    const int r_l = t >> 3;          // emission row (local)
    const int eq8 = (t & 7) * 8;     // emission e-chunk base

    while (true) {
        __syncthreads();             // also covers the weight preload on entry
        if (t == 0) sTask = atomicAdd(&g_counter, 1);
        __syncthreads();
        const int task = sTask;
        if (task >= NTASKS) break;

        const int p = task >> 2;           // longest-first: steps = 95 - p
        const int dir = (task >> 1) & 1;   // 0 = fwd, 1 = bwd
        const int half = task & 1;         // row half
        const int idx = dir ? 95 - p : p;

        // Initial state: sY[e*32+r] = x[b, idx, h, e], r_global = half*32 + r
        for (int q = t; q < 2048; q += NT) {
            int e = q >> 5, r = q & 31;
            int rg = half * 32 + r;
            int bb = rg >> 3, hh = rg & 7;
            sY[e * 32 + r] = __ldg(gx + (((bb * 96 + idx) * 8 + hh) << 6) + e);
        }

        // Per-thread x0 slice for emission
        const int rg = half * 32 + r_l;
        const int b = rg >> 3, h = rg & 7;
        float x0v[8];
        {
            const float* xp = gx + (((b * 96 + idx) * 8 + h) << 6) + eq8;
            float4 v0 = *(const float4*)xp;
            float4 v1 = *(const float4*)(xp + 4);
            x0v[0] = v0.x; x0v[1] = v0.y; x0v[2] = v0.z; x0v[3] = v0.w;
            x0v[4] = v1.x; x0v[5] = v1.y; x0v[6] = v1.z; x0v[7] = v1.w;
        }
        __syncthreads();

#define EMIT(J)                                                                     \
        {                                                                           \
            size_t ob = ((((size_t)b * 96 + idx) * 96 + (J)) * 8 + h) * 64 + eq8;   \
            _Pragma("unroll")                                                       \
            for (int i = 0; i < 8; i += 2) {                                        \
                float y0 = sY[(eq8 + i) * 32 + r_l];                                \
                float y1 = sY[(eq8 + i + 1) * 32 + r_l];                            \
                *(float4*)(out + ob + i) = make_float4(x0v[i], y0, x0v[i + 1], y1); \
            }                                                                       \
        }

#define STEP(DT)                                                                    \
        {                                                                           \
            const float dt_ = (DT);                                                 \
            gemm1(sY, sW1, sH, gb1, t, false); __syncthreads();                     \
            gemm2(0, dt_, sH, sW2, sY, sK1, sK2, gb2, t); __syncthreads();          \
            gemm1(sH, sW1, sH, gb1, t, true); __syncthreads();                      \
            gemm2(1, dt_, sH, sW2, sY, sK1, sK2, gb2, t); __syncthreads();          \
            gemm1(sH, sW1, sH, gb1, t, true); __syncthreads();                      \
            gemm2(2, dt_, sH, sW2, sY, sK1, sK2, gb2, t); __syncthreads();          \
            gemm1(sH, sW1, sH, gb1, t, true); __syncthreads();                      \
            gemm2(3, dt_, sH, sW2, sY, sK1, sK2, gb2, t); __syncthreads();          \
        }

        if (dir == 0) {
            EMIT(idx);
            for (int s = idx; s < 95; s++) {
                float dt = __ldg(gts + s + 1) - __ldg(gts + s);
                STEP(dt);
                EMIT(s + 1);
            }
        } else {
            for (int s = idx; s >= 1; s--) {
                float dt = __ldg(gts + s - 1) - __ldg(gts + s);   // negative
                STEP(dt);
                EMIT(s - 1);
            }
        }
#undef STEP
#undef EMIT
    }
}

extern "C" void kernel_launch(void* const* d_in, const int* in_sizes, int n_in,
                              void* d_out, int out_size)
{
    const float* x  = (const float*)d_in[0];
    const float* ts = (const float*)d_in[1];
    const float* W1 = (const float*)d_in[2];
    const float* b1 = (const float*)d_in[3];
    const float* W2 = (const float*)d_in[4];
    const float* b2 = (const float*)d_in[5];
    float2* out = (float2*)d_out;

    zero_counter_kernel<<<1, 1>>>();

    const int smem_bytes = (8192 * 2 + 4096 + 2048 * 3) * 4;   // 106496 B
    cudaFuncSetAttribute(ode_kernel,
                         cudaFuncAttributeMaxDynamicSharedMemorySize, smem_bytes);
    ode_kernel<<<296, NT, smem_bytes>>>(x, ts, W1, b1, W2, b2, out);
}

// round 9
// speedup vs baseline: 1.2895x; 1.2895x over previous
#include <cuda_runtime.h>

// B=8, L=96, H=8, E=64, EH=128. Rows per task = 32 (half of B*H=64).
#define NT 256
#define NTASKS 384
#define NSTATIC 148   // tasks 0..147 statically assigned to bid 0..147 (one per SM)

typedef unsigned long long ull;

__device__ int g_counter;

__global__ void zero_counter_kernel() { g_counter = 0; }

__device__ __forceinline__ ull pack2(float lo, float hi) {
    ull r; asm("mov.b64 %0, {%1, %2};" : "=l"(r) : "f"(lo), "f"(hi)); return r;
}
__device__ __forceinline__ void unpack2(ull v, float& lo, float& hi) {
    asm("mov.b64 {%0, %1}, %2;" : "=f"(lo), "=f"(hi) : "l"(v));
}
__device__ __forceinline__ void ffma2(ull& acc, ull a, ull b) {
    asm("fma.rn.f32x2 %0, %1, %2, %0;" : "+l"(acc) : "l"(a), "l"(b));
}
__device__ __forceinline__ float tanh_ap(float x) {
    float y; asm("tanh.approx.f32 %0, %1;" : "=f"(y) : "f"(x)); return y;
}

// GEMM1 + tanh: sH[c*32+r] = tanh(b1[c] + sum_k A[k*32+r] * sW1[k*128+c])
// r<32, c<128, k<64. 256 threads, tile 2 rows x 8 cols.
// A may alias sH[0:2048] (the arg region); ibar=true inserts the barrier
// between the (complete) read phase and the write phase.
__device__ __noinline__ void gemm1(const float* A,
                                   const float* __restrict__ sW1,
                                   float* sH,
                                   const float* __restrict__ gb1,
                                   int t, bool ibar)
{
    const int r0 = (t & 15) * 2;
    const int c0 = (t >> 4) * 8;
    ull acc[2][4];
#pragma unroll
    for (int j = 0; j < 4; j++) {
        ull b = pack2(__ldg(gb1 + c0 + 2 * j), __ldg(gb1 + c0 + 2 * j + 1));
        acc[0][j] = b; acc[1][j] = b;
    }
#pragma unroll 16
    for (int k = 0; k < 64; k++) {
        float2 a = *(const float2*)(A + k * 32 + r0);
        ull ap0 = pack2(a.x, a.x), ap1 = pack2(a.y, a.y);
        ulonglong2 w01 = *(const ulonglong2*)(sW1 + k * 128 + c0);
        ulonglong2 w23 = *(const ulonglong2*)(sW1 + k * 128 + c0 + 4);
        ffma2(acc[0][0], ap0, w01.x); ffma2(acc[0][1], ap0, w01.y);
        ffma2(acc[0][2], ap0, w23.x); ffma2(acc[0][3], ap0, w23.y);
        ffma2(acc[1][0], ap1, w01.x); ffma2(acc[1][1], ap1, w01.y);
        ffma2(acc[1][2], ap1, w23.x); ffma2(acc[1][3], ap1, w23.y);
    }
    if (ibar) __syncthreads();
#pragma unroll
    for (int j = 0; j < 4; j++) {
        float l0, h0, l1, h1;
        unpack2(acc[0][j], l0, h0);
        unpack2(acc[1][j], l1, h1);
        *(float2*)(sH + (c0 + 2 * j) * 32 + r0)     = make_float2(tanh_ap(l0), tanh_ap(l1));
        *(float2*)(sH + (c0 + 2 * j + 1) * 32 + r0) = make_float2(tanh_ap(h0), tanh_ap(h1));
    }
}

// GEMM2 + fused RK4 epilogue. k[e][r] = b2[e] + sum_c sH[c*32+r] * sW2[c*64+e]
// mode 0: sK1=k;             arg(=sH[0:2048]) = y + (dt/3) k
// mode 1: sK2=k;             arg = y + dt*k - (dt/3) k1
// mode 2: sK1 = k1+3(k2+k);  arg = y + dt*(k1 - k2 + k)
// mode 3: sY += (dt/8)*(S + k)    (S = sK1 from mode 2)
__device__ __noinline__ void gemm2(int mode, float dt,
                                   float* sH,
                                   const float* __restrict__ sW2,
                                   float* __restrict__ sY,
                                   float* __restrict__ sK1,
                                   float* __restrict__ sK2,
                                   const float* __restrict__ gb2,
                                   int t)
{
    const int r0 = (t & 15) * 2;
    const int e0 = (t >> 4) * 4;
    ull acc[2][2];
    {
        ull b0 = pack2(__ldg(gb2 + e0),     __ldg(gb2 + e0 + 1));
        ull b1 = pack2(__ldg(gb2 + e0 + 2), __ldg(gb2 + e0 + 3));
        acc[0][0] = b0; acc[1][0] = b0; acc[0][1] = b1; acc[1][1] = b1;
    }
#pragma unroll 16
    for (int c = 0; c < 128; c++) {
        float2 a = *(const float2*)(sH + c * 32 + r0);
        ull ap0 = pack2(a.x, a.x), ap1 = pack2(a.y, a.y);
        ulonglong2 w = *(const ulonglong2*)(sW2 + c * 64 + e0);
        ffma2(acc[0][0], ap0, w.x); ffma2(acc[0][1], ap0, w.y);
        ffma2(acc[1][0], ap1, w.x); ffma2(acc[1][1], ap1, w.y);
    }
    if (mode != 3) __syncthreads();
    float kv0[4], kv1[4];
    unpack2(acc[0][0], kv0[0], kv0[1]); unpack2(acc[0][1], kv0[2], kv0[3]);
    unpack2(acc[1][0], kv1[0], kv1[1]); unpack2(acc[1][1], kv1[2], kv1[3]);
    const float dt3 = dt * (1.0f / 3.0f);
    const float dt8 = dt * 0.125f;
#pragma unroll
    for (int j = 0; j < 4; j++) {
        const int ix = (e0 + j) * 32 + r0;
        float kx = kv0[j], ky = kv1[j];
        if (mode == 0) {
            float2 y = *(const float2*)(sY + ix);
            *(float2*)(sK1 + ix) = make_float2(kx, ky);
            *(float2*)(sH + ix) = make_float2(y.x + dt3 * kx, y.y + dt3 * ky);
        } else if (mode == 1) {
            float2 y  = *(const float2*)(sY + ix);
            float2 k1 = *(const float2*)(sK1 + ix);
            *(float2*)(sK2 + ix) = make_float2(kx, ky);
            *(float2*)(sH + ix) = make_float2(y.x + dt * kx - dt3 * k1.x,
                                              y.y + dt * ky - dt3 * k1.y);
        } else if (mode == 2) {
            float2 y  = *(const float2*)(sY + ix);
            float2 k1 = *(const float2*)(sK1 + ix);
            float2 k2 = *(const float2*)(sK2 + ix);
            *(float2*)(sK1 + ix) = make_float2(k1.x + 3.0f * (k2.x + kx),
                                               k1.y + 3.0f * (k2.y + ky));
            *(float2*)(sH + ix) = make_float2(y.x + dt * (k1.x - k2.x + kx),
                                              y.y + dt * (k1.y - k2.y + ky));
        } else {
            float2 y = *(const float2*)(sY + ix);
            float2 S = *(const float2*)(sK1 + ix);
            *(float2*)(sY + ix) = make_float2(y.x + dt8 * (S.x + kx),
                                              y.y + dt8 * (S.y + ky));
        }
    }
}

__global__ void __launch_bounds__(NT, 2) ode_kernel(
    const float* __restrict__ gx, const float* __restrict__ gts,
    const float* __restrict__ gW1, const float* __restrict__ gb1,
    const float* __restrict__ gW2, const float* __restrict__ gb2,
    float2* __restrict__ out)
{
    extern __shared__ float sm[];
    float* sW1 = sm;             // 8192  [k*128+c]
    float* sW2 = sW1 + 8192;     // 8192  [c*64+e]
    float* sH  = sW2 + 8192;     // 4096  [c*32+r]; first 2048 double as arg [e*32+r]
    float* sY  = sH + 4096;      // 2048  [e*32+r]
    float* sK1 = sY + 2048;      // 2048
    float* sK2 = sK1 + 2048;     // 2048
    __shared__ int sTask;

    const int t = threadIdx.x;
    for (int q = t; q < 8192; q += NT) { sW1[q] = gW1[q]; sW2[q] = gW2[q]; }

    const int r_l = t >> 3;          // emission row (local)
    const int eq8 = (t & 7) * 8;     // emission e-chunk base

    // Scheduling: bid % 148 selects a unique SM (classic-launch LUT). Slot-A
    // CTAs (bid < 148) take the bid-th longest chain statically, so no SM
    // hosts two long chains. Everyone then drains the short-task queue
    // (tasks NSTATIC..383, still longest-first) dynamically.
    bool first_pick = (blockIdx.x < NSTATIC);

    while (true) {
        __syncthreads();             // also covers the weight preload on entry
        if (t == 0) {
            int tk;
            if (first_pick) tk = blockIdx.x;
            else            tk = NSTATIC + atomicAdd(&g_counter, 1);
            sTask = tk;
        }
        first_pick = false;
        __syncthreads();
        const int task = sTask;
        if (task >= NTASKS) break;

        const int p = task >> 2;           // longest-first: steps = 95 - p
        const int dir = (task >> 1) & 1;   // 0 = fwd, 1 = bwd
        const int half = task & 1;         // row half
        const int idx = dir ? 95 - p : p;

        // Initial state: sY[e*32+r] = x[b, idx, h, e], r_global = half*32 + r
        for (int q = t; q < 2048; q += NT) {
            int e = q >> 5, r = q & 31;
            int rg = half * 32 + r;
            int bb = rg >> 3, hh = rg & 7;
            sY[e * 32 + r] = __ldg(gx + (((bb * 96 + idx) * 8 + hh) << 6) + e);
        }

        // Per-thread x0 slice for emission
        const int rg = half * 32 + r_l;
        const int b = rg >> 3, h = rg & 7;
        float x0v[8];
        {
            const float* xp = gx + (((b * 96 + idx) * 8 + h) << 6) + eq8;
            float4 v0 = *(const float4*)xp;
            float4 v1 = *(const float4*)(xp + 4);
            x0v[0] = v0.x; x0v[1] = v0.y; x0v[2] = v0.z; x0v[3] = v0.w;
            x0v[4] = v1.x; x0v[5] = v1.y; x0v[6] = v1.z; x0v[7] = v1.w;
        }
        __syncthreads();

#define EMIT(J)                                                                     \
        {                                                                           \
            size_t ob = ((((size_t)b * 96 + idx) * 96 + (J)) * 8 + h) * 64 + eq8;   \
            _Pragma("unroll")                                                       \
            for (int i = 0; i < 8; i += 2) {                                        \
                float y0 = sY[(eq8 + i) * 32 + r_l];                                \
                float y1 = sY[(eq8 + i + 1) * 32 + r_l];                            \
                *(float4*)(out + ob + i) = make_float4(x0v[i], y0, x0v[i + 1], y1); \
            }                                                                       \
        }

#define STEP(DT)                                                                    \
        {                                                                           \
            const float dt_ = (DT);                                                 \
            gemm1(sY, sW1, sH, gb1, t, false); __syncthreads();                     \
            gemm2(0, dt_, sH, sW2, sY, sK1, sK2, gb2, t); __syncthreads();          \
            gemm1(sH, sW1, sH, gb1, t, true); __syncthreads();                      \
            gemm2(1, dt_, sH, sW2, sY, sK1, sK2, gb2, t); __syncthreads();          \
            gemm1(sH, sW1, sH, gb1, t, true); __syncthreads();                      \
            gemm2(2, dt_, sH, sW2, sY, sK1, sK2, gb2, t); __syncthreads();          \
            gemm1(sH, sW1, sH, gb1, t, true); __syncthreads();                      \
            gemm2(3, dt_, sH, sW2, sY, sK1, sK2, gb2, t); __syncthreads();          \
        }

        if (dir == 0) {
            EMIT(idx);
            for (int s = idx; s < 95; s++) {
                float dt = __ldg(gts + s + 1) - __ldg(gts + s);
                STEP(dt);
                EMIT(s + 1);
            }
        } else {
            for (int s = idx; s >= 1; s--) {
                float dt = __ldg(gts + s - 1) - __ldg(gts + s);   // negative
                STEP(dt);
                EMIT(s - 1);
            }
        }
#undef STEP
#undef EMIT
    }
}

extern "C" void kernel_launch(void* const* d_in, const int* in_sizes, int n_in,
                              void* d_out, int out_size)
{
    const float* x  = (const float*)d_in[0];
    const float* ts = (const float*)d_in[1];
    const float* W1 = (const float*)d_in[2];
    const float* b1 = (const float*)d_in[3];
    const float* W2 = (const float*)d_in[4];
    const float* b2 = (const float*)d_in[5];
    float2* out = (float2*)d_out;

    zero_counter_kernel<<<1, 1>>>();

    const int smem_bytes = (8192 * 2 + 4096 + 2048 * 3) * 4;   // 106496 B
    cudaFuncSetAttribute(ode_kernel,
                         cudaFuncAttributeMaxDynamicSharedMemorySize, smem_bytes);
    ode_kernel<<<296, NT, smem_bytes>>>(x, ts, W1, b1, W2, b2, out);
}